// round 1
// baseline (speedup 1.0000x reference)
#include <cuda_runtime.h>
#include <math.h>

#define S_IMGC 2048
#define S_TXTC 512
#define S_TOTC 2560
#define DC     1536
#define HC     24
#define DHC    64

// Scratch (device globals: allocation-free rule)
__device__ float g_q[(size_t)HC * S_TOTC * DHC];
__device__ float g_k[(size_t)HC * S_TOTC * DHC];
__device__ float g_v[(size_t)HC * S_TOTC * DHC];
__device__ float g_ao[(size_t)S_TOTC * DC];

// ---------------------------------------------------------------------------
// Generic tiled GEMM: C[M x 1536] = X[M x 1536] * W[1536 x 1536]^T + bias
// mode 0: scatter into head-major qkv buffer [h][s_off+m][d] (n = h*64+d)
// mode 1: row-major out[m*DC + n]
// Tile 64x64, K-tile 16, 256 threads, 4x4 per thread.
// ---------------------------------------------------------------------------
__global__ __launch_bounds__(256) void gemm64(
    const float* __restrict__ X, const float* __restrict__ W,
    const float* __restrict__ bias, float* __restrict__ out,
    int s_off, int mode)
{
    __shared__ float As[16][68];
    __shared__ float Bs[16][68];
    const int tid  = threadIdx.x;
    const int tx   = tid & 15;
    const int ty   = tid >> 4;
    const int lrow = tid >> 2;        // 0..63
    const int lk   = (tid & 3) << 2;  // 0,4,8,12

    const float* Xp = X + (size_t)(blockIdx.y * 64 + lrow) * DC + lk;
    const float* Wp = W + (size_t)(blockIdx.x * 64 + lrow) * DC + lk;

    float acc[4][4] = {};

    for (int k0 = 0; k0 < DC; k0 += 16) {
        float4 a = *(const float4*)(Xp + k0);
        float4 b = *(const float4*)(Wp + k0);
        __syncthreads();  // previous iter's reads complete
        As[lk + 0][lrow] = a.x; As[lk + 1][lrow] = a.y;
        As[lk + 2][lrow] = a.z; As[lk + 3][lrow] = a.w;
        Bs[lk + 0][lrow] = b.x; Bs[lk + 1][lrow] = b.y;
        Bs[lk + 2][lrow] = b.z; Bs[lk + 3][lrow] = b.w;
        __syncthreads();
        #pragma unroll
        for (int k = 0; k < 16; ++k) {
            float4 av = *(const float4*)&As[k][ty << 2];
            float4 bv = *(const float4*)&Bs[k][tx << 2];
            float ar[4] = {av.x, av.y, av.z, av.w};
            float br[4] = {bv.x, bv.y, bv.z, bv.w};
            #pragma unroll
            for (int i = 0; i < 4; ++i)
                #pragma unroll
                for (int j = 0; j < 4; ++j)
                    acc[i][j] = fmaf(ar[i], br[j], acc[i][j]);
        }
    }

    #pragma unroll
    for (int i = 0; i < 4; ++i) {
        const int m = blockIdx.y * 64 + (ty << 2) + i;
        #pragma unroll
        for (int j = 0; j < 4; ++j) {
            const int n = blockIdx.x * 64 + (tx << 2) + j;
            const float v = acc[i][j] + bias[n];
            if (mode == 0) {
                const int h = n >> 6, d = n & 63;
                out[((size_t)h * S_TOTC + (s_off + m)) * DHC + d] = v;
            } else {
                out[(size_t)m * DC + n] = v;
            }
        }
    }
}

// ---------------------------------------------------------------------------
// Per-(h,s) RMS-norm + RoPE on q or k (in place). 1 block = 1 row, 32 threads
// (each thread owns the (2t, 2t+1) rotation pair).
// ---------------------------------------------------------------------------
__global__ __launch_bounds__(32) void rmsrope(
    float* __restrict__ buf,
    const float* __restrict__ cosb, const float* __restrict__ sinb,
    const float* __restrict__ gtxt, const float* __restrict__ gimg)
{
    const int s = blockIdx.x, h = blockIdx.y, t = threadIdx.x;
    float* p = buf + ((size_t)h * S_TOTC + s) * DHC;
    float x0 = p[2 * t], x1 = p[2 * t + 1];
    float ss = x0 * x0 + x1 * x1;
    #pragma unroll
    for (int o = 16; o; o >>= 1) ss += __shfl_xor_sync(0xffffffffu, ss, o);
    const float r = rsqrtf(ss * (1.0f / 64.0f) + 1e-6f);
    const float* g = (s < S_TXTC) ? gtxt : gimg;
    const float y0 = x0 * r * g[2 * t];
    const float y1 = x1 * r * g[2 * t + 1];
    const float c  = cosb[s * 64 + 2 * t];   // repeated pairs: [2t]==[2t+1]
    const float sn = sinb[s * 64 + 2 * t];
    p[2 * t]     = y0 * c - y1 * sn;
    p[2 * t + 1] = y1 * c + y0 * sn;
}

// ---------------------------------------------------------------------------
// Flash attention, fp32. 1 block = (head, 64-query tile), 64 threads,
// 1 thread = 1 query row. Online softmax in 16-wide chunks (sreg in regs).
// ---------------------------------------------------------------------------
__global__ __launch_bounds__(64) void attn_kernel()
{
    __shared__ float Ks[64][68];   // pad 68: 16B-aligned rows, no 32-way STS conflict
    __shared__ float Vs[64][68];
    const int h = blockIdx.y, qt = blockIdx.x, t = threadIdx.x;

    const float* qp = g_q + ((size_t)h * S_TOTC + qt * 64 + t) * DHC;
    float q[64];
    #pragma unroll
    for (int d = 0; d < 64; ++d) q[d] = qp[d] * 0.125f;  // DH^-0.5

    float m = -3.0e38f, l = 0.0f;
    float acc[64];
    #pragma unroll
    for (int d = 0; d < 64; ++d) acc[d] = 0.0f;

    for (int j0 = 0; j0 < S_TOTC; j0 += 64) {
        __syncthreads();
        const float* kp = g_k + ((size_t)h * S_TOTC + j0 + t) * DHC;
        const float* vp = g_v + ((size_t)h * S_TOTC + j0 + t) * DHC;
        #pragma unroll
        for (int d = 0; d < 64; d += 4) {
            *(float4*)&Ks[t][d] = *(const float4*)(kp + d);
            *(float4*)&Vs[t][d] = *(const float4*)(vp + d);
        }
        __syncthreads();

        #pragma unroll 1
        for (int jc = 0; jc < 64; jc += 16) {
            float sreg[16];
            float mn = m;
            #pragma unroll
            for (int j = 0; j < 16; ++j) {
                float s0 = 0.f, s1 = 0.f, s2 = 0.f, s3 = 0.f;
                #pragma unroll
                for (int d = 0; d < 64; d += 4) {
                    const float4 kv = *(const float4*)&Ks[jc + j][d];
                    s0 = fmaf(q[d + 0], kv.x, s0);
                    s1 = fmaf(q[d + 1], kv.y, s1);
                    s2 = fmaf(q[d + 2], kv.z, s2);
                    s3 = fmaf(q[d + 3], kv.w, s3);
                }
                sreg[j] = (s0 + s1) + (s2 + s3);
                mn = fmaxf(mn, sreg[j]);
            }
            const float corr = __expf(m - mn);
            m = mn;
            l *= corr;
            #pragma unroll
            for (int d = 0; d < 64; ++d) acc[d] *= corr;
            #pragma unroll
            for (int j = 0; j < 16; ++j) {
                const float p = __expf(sreg[j] - mn);
                l += p;
                #pragma unroll
                for (int d = 0; d < 64; d += 4) {
                    const float4 vv = *(const float4*)&Vs[jc + j][d];
                    acc[d + 0] = fmaf(p, vv.x, acc[d + 0]);
                    acc[d + 1] = fmaf(p, vv.y, acc[d + 1]);
                    acc[d + 2] = fmaf(p, vv.z, acc[d + 2]);
                    acc[d + 3] = fmaf(p, vv.w, acc[d + 3]);
                }
            }
        }
    }

    const float inv = 1.0f / l;
    float* op = g_ao + (size_t)(qt * 64 + t) * DC + h * DHC;
    #pragma unroll
    for (int d = 0; d < 64; d += 4) {
        float4 w;
        w.x = acc[d + 0] * inv; w.y = acc[d + 1] * inv;
        w.z = acc[d + 2] * inv; w.w = acc[d + 3] * inv;
        *(float4*)(op + d) = w;
    }
}

// ---------------------------------------------------------------------------
extern "C" void kernel_launch(void* const* d_in, const int* in_sizes, int n_in,
                              void* d_out, int out_size)
{
    (void)in_sizes; (void)n_in; (void)out_size;
    const float* hs  = (const float*)d_in[0];
    const float* ehs = (const float*)d_in[1];
    const float* rc  = (const float*)d_in[2];
    const float* rs  = (const float*)d_in[3];
    const float* Wq  = (const float*)d_in[4];  const float* bq  = (const float*)d_in[5];
    const float* Wk  = (const float*)d_in[6];  const float* bk  = (const float*)d_in[7];
    const float* Wv  = (const float*)d_in[8];  const float* bv  = (const float*)d_in[9];
    const float* Waq = (const float*)d_in[10]; const float* baq = (const float*)d_in[11];
    const float* Wak = (const float*)d_in[12]; const float* bak = (const float*)d_in[13];
    const float* Wav = (const float*)d_in[14]; const float* bav = (const float*)d_in[15];
    const float* Wo  = (const float*)d_in[16]; const float* bo  = (const float*)d_in[17];
    const float* Wao = (const float*)d_in[18]; const float* bao = (const float*)d_in[19];
    const float* gq  = (const float*)d_in[20]; const float* gk  = (const float*)d_in[21];
    const float* gaq = (const float*)d_in[22]; const float* gak = (const float*)d_in[23];
    float* out = (float*)d_out;

    float *qb, *kb, *vb, *aob;
    cudaGetSymbolAddress((void**)&qb,  g_q);
    cudaGetSymbolAddress((void**)&kb,  g_k);
    cudaGetSymbolAddress((void**)&vb,  g_v);
    cudaGetSymbolAddress((void**)&aob, g_ao);

    const dim3 blk(256);
    const dim3 grid_txt(DC / 64, S_TXTC / 64);  // (24, 8)
    const dim3 grid_img(DC / 64, S_IMGC / 64);  // (24, 32)

    // QKV projections (text segment -> s [0,512), image segment -> s [512,2560))
    gemm64<<<grid_txt, blk>>>(ehs, Waq, baq, qb, 0,   0);
    gemm64<<<grid_txt, blk>>>(ehs, Wak, bak, kb, 0,   0);
    gemm64<<<grid_txt, blk>>>(ehs, Wav, bav, vb, 0,   0);
    gemm64<<<grid_img, blk>>>(hs,  Wq,  bq,  qb, 512, 0);
    gemm64<<<grid_img, blk>>>(hs,  Wk,  bk,  kb, 512, 0);
    gemm64<<<grid_img, blk>>>(hs,  Wv,  bv,  vb, 512, 0);

    // RMS norm + RoPE on q and k
    const dim3 rr_grid(S_TOTC, HC);
    rmsrope<<<rr_grid, 32>>>(qb, rc, rs, gaq, gq);
    rmsrope<<<rr_grid, 32>>>(kb, rc, rs, gak, gk);

    // Attention
    attn_kernel<<<dim3(S_TOTC / 64, HC), 64>>>();

    // Output projections: img rows [512,2560) -> out[0:2048*DC),
    //                     txt rows [0,512)    -> out[2048*DC:)
    gemm64<<<grid_img, blk>>>(aob + (size_t)512 * DC, Wo,  bo,  out, 0, 1);
    gemm64<<<grid_txt, blk>>>(aob, Wao, bao, out + (size_t)S_IMGC * DC, 0, 1);
}